// round 1
// baseline (speedup 1.0000x reference)
#include <cuda_runtime.h>
#include <math.h>

// ---------------------------------------------------------------------------
// Problem constants (fixed shapes from reference)
//   b=2, L=4096, d=1024, h=16, n=64, p=64, chunk=64 -> c=64 chunks per batch
//   tokens = 8192, tiles = b*c*h = 2048
// Output: y (2*4096*1024 = 8388608 floats) then final_state (2*16*64*64 = 131072)
// ---------------------------------------------------------------------------

#define NTOK   8192
#define DMOD   1024
#define NHEADS 16
#define NTILE  2048     // b * 64 chunks * 16 heads
#define Y_ELEMS 8388608

// Scratch (device globals; allocation inside kernel_launch is forbidden)
__device__ float gXZ[NTOK * 2048];       // x@W_in^T : [tok][2048] (x_in | z)
__device__ float gDt[NTOK * NHEADS];     // softplus dt : [tok][h]
__device__ float gB[NTOK * DMOD];        // x@W_B^T : [tok][h*64+n]
__device__ float gC[NTOK * DMOD];        // x@W_C^T
__device__ float gYdiag[NTILE * 4096];   // per-tile Y_diag [l][p]
__device__ float gStates[NTILE * 4096];  // per-tile chunk-end states [p][n]
__device__ float gStateIn[NTILE * 4096]; // state entering each chunk [p][n]
__device__ float gAlast[NTILE];          // A_cumsum at l=63 per tile
__device__ float gYact[NTOK * DMOD];     // (Y_diag+Y_off)*silu(z)

// ---------------------------------------------------------------------------
// Generic SGEMM: C[m][n] = sum_k A[m*K+k] * B[n*K+k]   (A row-major MxK,
// B row-major NxK i.e. computes A @ B^T). M%128==0, N%128==0, K%16==0.
// 128x128 tile, 256 threads, 8x8 register micro-tile.
// ---------------------------------------------------------------------------
__global__ __launch_bounds__(256, 2)
void gemm_nt(const float* __restrict__ A, const float* __restrict__ B,
             float* __restrict__ C, int M, int N, int K) {
    __shared__ float As[16][128];
    __shared__ float Bs[16][128];
    const int t  = threadIdx.x;
    const int bm = blockIdx.y * 128;
    const int bn = blockIdx.x * 128;
    const int tx = t & 15, ty = t >> 4;
    const int lr = t >> 2;          // 0..63
    const int lc = (t & 3) << 2;    // 0,4,8,12

    float acc[8][8];
#pragma unroll
    for (int i = 0; i < 8; i++)
#pragma unroll
        for (int j = 0; j < 8; j++) acc[i][j] = 0.f;

    const float* Ab = A + (size_t)bm * K;
    const float* Bb = B + (size_t)bn * K;

    for (int k0 = 0; k0 < K; k0 += 16) {
        float4 a0 = *(const float4*)&Ab[(size_t)lr * K + k0 + lc];
        float4 a1 = *(const float4*)&Ab[(size_t)(lr + 64) * K + k0 + lc];
        float4 b0 = *(const float4*)&Bb[(size_t)lr * K + k0 + lc];
        float4 b1 = *(const float4*)&Bb[(size_t)(lr + 64) * K + k0 + lc];
        As[lc + 0][lr] = a0.x; As[lc + 1][lr] = a0.y; As[lc + 2][lr] = a0.z; As[lc + 3][lr] = a0.w;
        As[lc + 0][lr + 64] = a1.x; As[lc + 1][lr + 64] = a1.y; As[lc + 2][lr + 64] = a1.z; As[lc + 3][lr + 64] = a1.w;
        Bs[lc + 0][lr] = b0.x; Bs[lc + 1][lr] = b0.y; Bs[lc + 2][lr] = b0.z; Bs[lc + 3][lr] = b0.w;
        Bs[lc + 0][lr + 64] = b1.x; Bs[lc + 1][lr + 64] = b1.y; Bs[lc + 2][lr + 64] = b1.z; Bs[lc + 3][lr + 64] = b1.w;
        __syncthreads();
#pragma unroll
        for (int k = 0; k < 16; k++) {
            float4 aa0 = *(const float4*)&As[k][ty * 8];
            float4 aa1 = *(const float4*)&As[k][ty * 8 + 4];
            float4 bb0 = *(const float4*)&Bs[k][tx * 8];
            float4 bb1 = *(const float4*)&Bs[k][tx * 8 + 4];
            float a[8] = {aa0.x, aa0.y, aa0.z, aa0.w, aa1.x, aa1.y, aa1.z, aa1.w};
            float b[8] = {bb0.x, bb0.y, bb0.z, bb0.w, bb1.x, bb1.y, bb1.z, bb1.w};
#pragma unroll
            for (int i = 0; i < 8; i++)
#pragma unroll
                for (int j = 0; j < 8; j++) acc[i][j] += a[i] * b[j];
        }
        __syncthreads();
    }
#pragma unroll
    for (int i = 0; i < 8; i++) {
        size_t row = bm + ty * 8 + i;
        float4* cp = (float4*)&C[row * N + bn + tx * 8];
        cp[0] = make_float4(acc[i][0], acc[i][1], acc[i][2], acc[i][3]);
        cp[1] = make_float4(acc[i][4], acc[i][5], acc[i][6], acc[i][7]);
    }
}

// ---------------------------------------------------------------------------
// dt[tok][h] = softplus( dot(x[tok], W_dt[h]) + b_dt[h] )
// one block per token, one warp per head (16 warps = 512 threads)
// ---------------------------------------------------------------------------
__global__ __launch_bounds__(512)
void dt_kernel(const float* __restrict__ x, const float* __restrict__ Wdt,
               const float* __restrict__ bdt) {
    const int tok  = blockIdx.x;
    const int head = threadIdx.x >> 5;
    const int lane = threadIdx.x & 31;
    const float* xr = x + (size_t)tok * DMOD;
    const float* wr = Wdt + (size_t)head * DMOD;
    float s = 0.f;
#pragma unroll 8
    for (int i = lane; i < DMOD; i += 32) s += xr[i] * wr[i];
#pragma unroll
    for (int o = 16; o > 0; o >>= 1) s += __shfl_down_sync(0xffffffffu, s, o);
    if (lane == 0) {
        float v  = s + bdt[head];
        float sp = (v > 20.f) ? v : log1pf(expf(v));
        gDt[tok * NHEADS + head] = sp;
    }
}

// ---------------------------------------------------------------------------
// SSD pass 1: per (b, chunk, head) tile -> Y_diag, chunk-end states, A_last
// ---------------------------------------------------------------------------
__global__ __launch_bounds__(256)
void ssd_pass1(const float* __restrict__ Alog) {
    extern __shared__ float sm[];
    float* sB = sm;                 // [64][65]
    float* sC = sm + 64 * 65;       // [64][65], later holds G
    float* sX = sm + 2 * 64 * 65;   // [64][65]
    __shared__ float sdt[64];
    __shared__ float sacum[64];
    __shared__ float sdec[64];

    const int tile = blockIdx.x;
    const int h = tile & 15;
    const int c = (tile >> 4) & 63;
    const int b = tile >> 10;
    const int t = threadIdx.x;
    const int tokb = b * 4096 + c * 64;

    if (t < 64) sdt[t] = gDt[(size_t)(tokb + t) * NHEADS + h];
    __syncthreads();
    if (t == 0) {
        float expA = expf(Alog[h]);
        float run = 0.f;
        for (int l = 0; l < 64; l++) { run -= expA * sdt[l]; sacum[l] = run; }
    }
#pragma unroll
    for (int k = 0; k < 16; k++) {
        int idx = t + k * 256;
        int l = idx >> 6, n = idx & 63;
        size_t tok = (size_t)(tokb + l);
        sB[l * 65 + n] = gB[tok * DMOD + h * 64 + n];
        sC[l * 65 + n] = gC[tok * DMOD + h * 64 + n];
        sX[l * 65 + n] = gXZ[tok * 2048 + h * 64 + n] * sdt[l];
    }
    __syncthreads();
    if (t < 64) sdec[t] = expf(sacum[63] - sacum[t]);

    const int ty = t >> 4, tx = t & 15;
    const int r0 = ty * 4, c0 = tx * 4;

    // G[l][s] = dot(C[l], B[s]) * exp(acum[l]-acum[s]) for s<=l else 0
    float g[4][4] = {};
#pragma unroll 4
    for (int n = 0; n < 64; n++) {
        float a[4], bb[4];
#pragma unroll
        for (int i = 0; i < 4; i++) a[i]  = sC[(r0 + i) * 65 + n];
#pragma unroll
        for (int j = 0; j < 4; j++) bb[j] = sB[(c0 + j) * 65 + n];
#pragma unroll
        for (int i = 0; i < 4; i++)
#pragma unroll
            for (int j = 0; j < 4; j++) g[i][j] += a[i] * bb[j];
    }
#pragma unroll
    for (int i = 0; i < 4; i++)
#pragma unroll
        for (int j = 0; j < 4; j++) {
            int l = r0 + i, s = c0 + j;
            g[i][j] = (s <= l) ? g[i][j] * expf(sacum[l] - sacum[s]) : 0.f;
        }
    __syncthreads();
#pragma unroll
    for (int i = 0; i < 4; i++)
#pragma unroll
        for (int j = 0; j < 4; j++) sC[(r0 + i) * 65 + c0 + j] = g[i][j];
    __syncthreads();

    // Y_diag = G @ X
    float yd[4][4] = {};
#pragma unroll 4
    for (int s = 0; s < 64; s++) {
        float a[4], bb[4];
#pragma unroll
        for (int i = 0; i < 4; i++) a[i]  = sC[(r0 + i) * 65 + s];
#pragma unroll
        for (int j = 0; j < 4; j++) bb[j] = sX[s * 65 + c0 + j];
#pragma unroll
        for (int i = 0; i < 4; i++)
#pragma unroll
            for (int j = 0; j < 4; j++) yd[i][j] += a[i] * bb[j];
    }
    // states[p][n] = sum_l X[l][p] * dec[l] * B[l][n]
    float st[4][4] = {};
#pragma unroll 4
    for (int l = 0; l < 64; l++) {
        float d = sdec[l];
        float a[4], bb[4];
#pragma unroll
        for (int i = 0; i < 4; i++) a[i]  = sX[l * 65 + r0 + i] * d;
#pragma unroll
        for (int j = 0; j < 4; j++) bb[j] = sB[l * 65 + c0 + j];
#pragma unroll
        for (int i = 0; i < 4; i++)
#pragma unroll
            for (int j = 0; j < 4; j++) st[i][j] += a[i] * bb[j];
    }
    size_t obase = (size_t)tile * 4096;
#pragma unroll
    for (int i = 0; i < 4; i++)
#pragma unroll
        for (int j = 0; j < 4; j++) {
            gYdiag[obase + (r0 + i) * 64 + c0 + j]  = yd[i][j];
            gStates[obase + (r0 + i) * 64 + c0 + j] = st[i][j];
        }
    if (t == 0) gAlast[tile] = sacum[63];
}

// ---------------------------------------------------------------------------
// Chunk-level scan over c (sequential recurrence per (b,h)); also emits the
// final state into d_out tail.  T_{c+1} = exp(A_last[c]) * T_c + states_c
// ---------------------------------------------------------------------------
__global__ __launch_bounds__(256)
void scan_kernel(float* __restrict__ out_final) {
    const int bh = blockIdx.x;       // 0..31
    const int b = bh >> 4, h = bh & 15;
    const int t = threadIdx.x;
    float S[16];
#pragma unroll
    for (int k = 0; k < 16; k++) S[k] = 0.f;
    for (int c = 0; c < 64; c++) {
        int tile = (b * 64 + c) * 16 + h;
        size_t base = (size_t)tile * 4096;
        float d = expf(gAlast[tile]);
#pragma unroll
        for (int k = 0; k < 16; k++) {
            int e = t + k * 256;
            gStateIn[base + e] = S[k];
            S[k] = S[k] * d + gStates[base + e];
        }
    }
    size_t ob = (size_t)Y_ELEMS + (size_t)(b * 16 + h) * 4096;
#pragma unroll
    for (int k = 0; k < 16; k++) out_final[ob + t + k * 256] = S[k];
}

// ---------------------------------------------------------------------------
// SSD pass 2: Y_off = exp(acum[l]) * (C @ StateIn^T); Y=(Yd+Yoff)*silu(z)
// ---------------------------------------------------------------------------
__global__ __launch_bounds__(256)
void ssd_pass2(const float* __restrict__ Alog) {
    __shared__ float sC[64 * 65];
    __shared__ float sS[64 * 65];
    __shared__ float sdt[64];
    __shared__ float sacum[64];

    const int tile = blockIdx.x;
    const int h = tile & 15;
    const int c = (tile >> 4) & 63;
    const int b = tile >> 10;
    const int t = threadIdx.x;
    const int tokb = b * 4096 + c * 64;

    if (t < 64) sdt[t] = gDt[(size_t)(tokb + t) * NHEADS + h];
    __syncthreads();
    if (t == 0) {
        float expA = expf(Alog[h]);
        float run = 0.f;
        for (int l = 0; l < 64; l++) { run -= expA * sdt[l]; sacum[l] = run; }
    }
    size_t sbase = (size_t)tile * 4096;
#pragma unroll
    for (int k = 0; k < 16; k++) {
        int idx = t + k * 256;
        int l = idx >> 6, n = idx & 63;
        sC[l * 65 + n] = gC[(size_t)(tokb + l) * DMOD + h * 64 + n];
        sS[l * 65 + n] = gStateIn[sbase + idx];   // [p][n]
    }
    __syncthreads();

    const int ty = t >> 4, tx = t & 15;
    const int r0 = ty * 4, c0 = tx * 4;   // rows l, cols p
    float o[4][4] = {};
#pragma unroll 4
    for (int n = 0; n < 64; n++) {
        float a[4], bb[4];
#pragma unroll
        for (int i = 0; i < 4; i++) a[i]  = sC[(r0 + i) * 65 + n];
#pragma unroll
        for (int j = 0; j < 4; j++) bb[j] = sS[(c0 + j) * 65 + n];
#pragma unroll
        for (int i = 0; i < 4; i++)
#pragma unroll
            for (int j = 0; j < 4; j++) o[i][j] += a[i] * bb[j];
    }
#pragma unroll
    for (int i = 0; i < 4; i++) {
        int l = r0 + i;
        size_t tok = (size_t)(tokb + l);
        float eA = expf(sacum[l]);
#pragma unroll
        for (int j = 0; j < 4; j++) {
            int p = c0 + j;
            int dcol = h * 64 + p;
            float yv = gYdiag[sbase + l * 64 + p] + o[i][j] * eA;
            float zv = gXZ[tok * 2048 + 1024 + dcol];
            float sig = 1.f / (1.f + expf(-zv));
            gYact[tok * DMOD + dcol] = yv * (zv * sig);
        }
    }
}

// ---------------------------------------------------------------------------
extern "C" void kernel_launch(void* const* d_in, const int* in_sizes, int n_in,
                              void* d_out, int out_size) {
    const float* x     = (const float*)d_in[0];
    const float* W_in  = (const float*)d_in[1];
    const float* W_dt  = (const float*)d_in[2];
    const float* b_dt  = (const float*)d_in[3];
    const float* W_B   = (const float*)d_in[4];
    const float* W_C   = (const float*)d_in[5];
    const float* W_out = (const float*)d_in[6];
    const float* A_log = (const float*)d_in[7];
    float* out = (float*)d_out;

    void *pXZ, *pB, *pC, *pYa;
    cudaGetSymbolAddress(&pXZ, gXZ);
    cudaGetSymbolAddress(&pB,  gB);
    cudaGetSymbolAddress(&pC,  gC);
    cudaGetSymbolAddress(&pYa, gYact);

    const int P1_SHMEM = 3 * 64 * 65 * (int)sizeof(float);   // 49920 B
    cudaFuncSetAttribute(ssd_pass1, cudaFuncAttributeMaxDynamicSharedMemorySize,
                         P1_SHMEM);

    dim3 blk(256);
    // 1) xz = x @ W_in^T  (8192 x 2048)
    gemm_nt<<<dim3(2048 / 128, NTOK / 128), blk>>>(x, W_in, (float*)pXZ, NTOK, 2048, DMOD);
    // 2) dt
    dt_kernel<<<NTOK, 512>>>(x, W_dt, b_dt);
    // 3) B, C projections (8192 x 1024)
    gemm_nt<<<dim3(1024 / 128, NTOK / 128), blk>>>(x, W_B, (float*)pB, NTOK, DMOD, DMOD);
    gemm_nt<<<dim3(1024 / 128, NTOK / 128), blk>>>(x, W_C, (float*)pC, NTOK, DMOD, DMOD);
    // 4) per-tile diag output + chunk states
    ssd_pass1<<<NTILE, 256, P1_SHMEM>>>(A_log);
    // 5) chunk-level scan (also writes final state to d_out tail)
    scan_kernel<<<32, 256>>>(out);
    // 6) off-diagonal contribution + silu gating
    ssd_pass2<<<NTILE, 256>>>(A_log);
    // 7) y = Yact @ W_out^T  -> d_out head
    gemm_nt<<<dim3(1024 / 128, NTOK / 128), blk>>>((const float*)pYa, W_out, out, NTOK, DMOD, DMOD);
}

// round 3
// speedup vs baseline: 2.5602x; 2.5602x over previous
#include <cuda_runtime.h>
#include <cuda_bf16.h>
#include <math.h>
#include <stdint.h>

// ---------------------------------------------------------------------------
// Shapes: b=2, L=4096, d=1024, h=16, n=p=64, chunk=64 -> tokens 8192, tiles 2048
// Output: y (8388608 f32) then final_state (131072 f32)
// ---------------------------------------------------------------------------
#define NTOK   8192
#define DMOD   1024
#define NHEADS 16
#define NTILE  2048
#define Y_ELEMS 8388608

// fp32 scratch
__device__ float gXZ[NTOK * 2048];
__device__ float gDt[NTOK * NHEADS];
__device__ float gB[NTOK * DMOD];
__device__ float gC[NTOK * DMOD];
__device__ float gYdiag[NTILE * 4096];
__device__ float gStates[NTILE * 4096];
__device__ float gStateIn[NTILE * 4096];
__device__ float gAlast[NTILE];

// bf16 hi/lo operand scratch
__device__ __nv_bfloat16 gXhi[NTOK * DMOD], gXlo[NTOK * DMOD];
__device__ __nv_bfloat16 gWinHi[2048 * DMOD], gWinLo[2048 * DMOD];
__device__ __nv_bfloat16 gWBHi[DMOD * DMOD], gWBLo[DMOD * DMOD];
__device__ __nv_bfloat16 gWCHi[DMOD * DMOD], gWCLo[DMOD * DMOD];
__device__ __nv_bfloat16 gWoHi[DMOD * DMOD], gWoLo[DMOD * DMOD];
__device__ __nv_bfloat16 gYaHi[NTOK * DMOD], gYaLo[NTOK * DMOD];

// ---------------------------------------------------------------------------
// Helpers (sm_80-level PTX only: cp.async, ldmatrix, mma.sync)
// ---------------------------------------------------------------------------
__device__ __forceinline__ uint32_t smem_u32(const void* p) {
    uint32_t a;
    asm("{ .reg .u64 t; cvta.to.shared.u64 t, %1; cvt.u32.u64 %0, t; }" : "=r"(a) : "l"(p));
    return a;
}
#define SW128(o) ((o) ^ (((o) >> 3) & 0x70))

__device__ __forceinline__ void cp16(uint32_t dst, const void* src) {
    asm volatile("cp.async.cg.shared.global [%0], [%1], 16;\n" :: "r"(dst), "l"(src));
}
__device__ __forceinline__ void cp_commit() { asm volatile("cp.async.commit_group;\n" ::: "memory"); }
template <int N> __device__ __forceinline__ void cp_wait() {
    asm volatile("cp.async.wait_group %0;\n" :: "n"(N) : "memory");
}
__device__ __forceinline__ void ldsm4(uint32_t* r, uint32_t addr) {
    asm volatile("ldmatrix.sync.aligned.m8n8.x4.shared.b16 {%0,%1,%2,%3}, [%4];"
                 : "=r"(r[0]), "=r"(r[1]), "=r"(r[2]), "=r"(r[3]) : "r"(addr));
}
__device__ __forceinline__ void mma16816(float* d, const uint32_t* a, const uint32_t* b) {
    asm volatile("mma.sync.aligned.m16n8k16.row.col.f32.bf16.bf16.f32 "
                 "{%0,%1,%2,%3}, {%4,%5,%6,%7}, {%8,%9}, {%0,%1,%2,%3};"
                 : "+f"(d[0]), "+f"(d[1]), "+f"(d[2]), "+f"(d[3])
                 : "r"(a[0]), "r"(a[1]), "r"(a[2]), "r"(a[3]), "r"(b[0]), "r"(b[1]));
}

// ---------------------------------------------------------------------------
// Tensor-core GEMM via mma.sync: C[M,N] = A[M,K] @ B[N,K]^T, fp32 via bf16
// hi/lo 3-term emulation. CTA tile 128x128, K chunk 64, double buffered.
// 8 warps = 2(m) x 4(n); warp tile 64x32.
// ---------------------------------------------------------------------------
#define OF_AH 0
#define OF_AL 16384
#define OF_BH 32768
#define OF_BL 49152
#define STG   65536
#define GEMM_SMEM (2 * STG)

__device__ __forceinline__ void load_rows(uint32_t smem_dst, const __nv_bfloat16* g,
                                          int row0, int K, int k0, int t) {
#pragma unroll
    for (int it = 0; it < 4; it++) {
        int p = t + it * 256;               // 1024 16B-transfers for 128x64 bf16
        int r = p >> 3, cc = p & 7;
        uint32_t off = (uint32_t)(r * 128 + cc * 16);
        cp16(smem_dst + SW128(off), g + (size_t)(row0 + r) * K + k0 + cc * 8);
    }
}

__global__ __launch_bounds__(256)
void gemm_mma(const __nv_bfloat16* __restrict__ Ah, const __nv_bfloat16* __restrict__ Al,
              const __nv_bfloat16* __restrict__ Bh, const __nv_bfloat16* __restrict__ Bl,
              float* __restrict__ C, int M, int N, int K) {
    extern __shared__ char smem[];
    const uint32_t sb = smem_u32(smem);
    const int t = threadIdx.x;
    const int wid = t >> 5, lane = t & 31;
    const int bm = blockIdx.y * 128;
    const int bn = blockIdx.x * 128;
    const int wm = (wid >> 2) * 64;     // warp row base within CTA tile
    const int wn = (wid & 3) * 32;      // warp col base
    const int nch = K >> 6;

    float acc[4][4][4];
#pragma unroll
    for (int i = 0; i < 4; i++)
#pragma unroll
        for (int j = 0; j < 4; j++)
#pragma unroll
            for (int k = 0; k < 4; k++) acc[i][j][k] = 0.f;

    // prologue: chunk 0 -> stage 0
    {
        uint32_t st = sb;
        load_rows(st + OF_AH, Ah, bm, K, 0, t);
        load_rows(st + OF_AL, Al, bm, K, 0, t);
        load_rows(st + OF_BH, Bh, bn, K, 0, t);
        load_rows(st + OF_BL, Bl, bn, K, 0, t);
        cp_commit();
    }

    for (int i = 0; i < nch; i++) {
        if (i + 1 < nch) {
            uint32_t st2 = sb + ((i + 1) & 1) * STG;
            int k0 = (i + 1) * 64;
            load_rows(st2 + OF_AH, Ah, bm, K, k0, t);
            load_rows(st2 + OF_AL, Al, bm, K, k0, t);
            load_rows(st2 + OF_BH, Bh, bn, K, k0, t);
            load_rows(st2 + OF_BL, Bl, bn, K, k0, t);
            cp_commit();
            cp_wait<1>();
        } else {
            cp_wait<0>();
        }
        __syncthreads();
        const uint32_t st = sb + (i & 1) * STG;

#pragma unroll
        for (int kk = 0; kk < 4; kk++) {
            uint32_t ah[4][4], al[4][4], bhn[2][4], bln[2][4];
#pragma unroll
            for (int mi = 0; mi < 4; mi++) {
                int row = wm + mi * 16 + (lane & 15);
                uint32_t off = (uint32_t)(row * 128 + kk * 32 + ((lane >> 4) << 4));
                ldsm4(ah[mi], st + OF_AH + SW128(off));
                ldsm4(al[mi], st + OF_AL + SW128(off));
            }
#pragma unroll
            for (int nb = 0; nb < 2; nb++) {
                int rown = wn + nb * 16 + (lane & 7) + (((lane >> 4) & 1) << 3);
                uint32_t off = (uint32_t)(rown * 128 + kk * 32 + (((lane >> 3) & 1) << 4));
                ldsm4(bhn[nb], st + OF_BH + SW128(off));
                ldsm4(bln[nb], st + OF_BL + SW128(off));
            }
#pragma unroll
            for (int mi = 0; mi < 4; mi++)
#pragma unroll
                for (int ni = 0; ni < 4; ni++) {
                    const uint32_t* b2h = &bhn[ni >> 1][(ni & 1) * 2];
                    const uint32_t* b2l = &bln[ni >> 1][(ni & 1) * 2];
                    mma16816(acc[mi][ni], ah[mi], b2h);
                    mma16816(acc[mi][ni], ah[mi], b2l);
                    mma16816(acc[mi][ni], al[mi], b2h);
                }
        }
        __syncthreads();
    }

    // epilogue
#pragma unroll
    for (int mi = 0; mi < 4; mi++) {
        int r0 = bm + wm + mi * 16 + (lane >> 2);
#pragma unroll
        for (int ni = 0; ni < 4; ni++) {
            int c0 = bn + wn + ni * 8 + ((lane & 3) << 1);
            *(float2*)&C[(size_t)r0 * N + c0] = make_float2(acc[mi][ni][0], acc[mi][ni][1]);
            *(float2*)&C[(size_t)(r0 + 8) * N + c0] = make_float2(acc[mi][ni][2], acc[mi][ni][3]);
        }
    }
}

// ---------------------------------------------------------------------------
// fp32 -> bf16 hi/lo split
// ---------------------------------------------------------------------------
__global__ __launch_bounds__(256)
void cvt_hilo(const float* __restrict__ src, __nv_bfloat16* __restrict__ hi,
              __nv_bfloat16* __restrict__ lo, int n4) {
    int i = blockIdx.x * 256 + threadIdx.x;
    if (i >= n4) return;
    float4 v = ((const float4*)src)[i];
    __nv_bfloat16 h0 = __float2bfloat16(v.x), h1 = __float2bfloat16(v.y);
    __nv_bfloat16 h2 = __float2bfloat16(v.z), h3 = __float2bfloat16(v.w);
    __nv_bfloat162* hp = (__nv_bfloat162*)hi;
    __nv_bfloat162* lp = (__nv_bfloat162*)lo;
    hp[2 * i]     = __nv_bfloat162(h0, h1);
    hp[2 * i + 1] = __nv_bfloat162(h2, h3);
    lp[2 * i]     = __nv_bfloat162(__float2bfloat16(v.x - __bfloat162float(h0)),
                                   __float2bfloat16(v.y - __bfloat162float(h1)));
    lp[2 * i + 1] = __nv_bfloat162(__float2bfloat16(v.z - __bfloat162float(h2)),
                                   __float2bfloat16(v.w - __bfloat162float(h3)));
}

// ---------------------------------------------------------------------------
// dt[tok][h] = softplus(x . W_dt[h] + b_dt[h])
// ---------------------------------------------------------------------------
__global__ __launch_bounds__(512)
void dt_kernel(const float* __restrict__ x, const float* __restrict__ Wdt,
               const float* __restrict__ bdt) {
    const int tok  = blockIdx.x;
    const int head = threadIdx.x >> 5;
    const int lane = threadIdx.x & 31;
    const float* xr = x + (size_t)tok * DMOD;
    const float* wr = Wdt + (size_t)head * DMOD;
    float s = 0.f;
#pragma unroll 8
    for (int i = lane; i < DMOD; i += 32) s += xr[i] * wr[i];
#pragma unroll
    for (int o = 16; o > 0; o >>= 1) s += __shfl_down_sync(0xffffffffu, s, o);
    if (lane == 0) {
        float v  = s + bdt[head];
        float sp = (v > 20.f) ? v : log1pf(expf(v));
        gDt[tok * NHEADS + head] = sp;
    }
}

// ---------------------------------------------------------------------------
// SSD pass 1: per (b, chunk, head) tile -> Y_diag, chunk-end states, A_last
// ---------------------------------------------------------------------------
__global__ __launch_bounds__(256)
void ssd_pass1(const float* __restrict__ Alog) {
    extern __shared__ float sm[];
    float* sB = sm;
    float* sC = sm + 64 * 65;
    float* sX = sm + 2 * 64 * 65;
    __shared__ float sdt[64];
    __shared__ float sacum[64];
    __shared__ float sdec[64];

    const int tile = blockIdx.x;
    const int h = tile & 15;
    const int c = (tile >> 4) & 63;
    const int b = tile >> 10;
    const int t = threadIdx.x;
    const int tokb = b * 4096 + c * 64;

    if (t < 64) sdt[t] = gDt[(size_t)(tokb + t) * NHEADS + h];
    __syncthreads();
    if (t == 0) {
        float expA = expf(Alog[h]);
        float run = 0.f;
        for (int l = 0; l < 64; l++) { run -= expA * sdt[l]; sacum[l] = run; }
    }
#pragma unroll
    for (int k = 0; k < 16; k++) {
        int idx = t + k * 256;
        int l = idx >> 6, n = idx & 63;
        size_t tok = (size_t)(tokb + l);
        sB[l * 65 + n] = gB[tok * DMOD + h * 64 + n];
        sC[l * 65 + n] = gC[tok * DMOD + h * 64 + n];
        sX[l * 65 + n] = gXZ[tok * 2048 + h * 64 + n] * sdt[l];
    }
    __syncthreads();
    if (t < 64) sdec[t] = expf(sacum[63] - sacum[t]);

    const int ty = t >> 4, tx = t & 15;
    const int r0 = ty * 4, c0 = tx * 4;

    float g[4][4] = {};
#pragma unroll 4
    for (int n = 0; n < 64; n++) {
        float a[4], bb[4];
#pragma unroll
        for (int i = 0; i < 4; i++) a[i]  = sC[(r0 + i) * 65 + n];
#pragma unroll
        for (int j = 0; j < 4; j++) bb[j] = sB[(c0 + j) * 65 + n];
#pragma unroll
        for (int i = 0; i < 4; i++)
#pragma unroll
            for (int j = 0; j < 4; j++) g[i][j] += a[i] * bb[j];
    }
#pragma unroll
    for (int i = 0; i < 4; i++)
#pragma unroll
        for (int j = 0; j < 4; j++) {
            int l = r0 + i, s = c0 + j;
            g[i][j] = (s <= l) ? g[i][j] * expf(sacum[l] - sacum[s]) : 0.f;
        }
    __syncthreads();
#pragma unroll
    for (int i = 0; i < 4; i++)
#pragma unroll
        for (int j = 0; j < 4; j++) sC[(r0 + i) * 65 + c0 + j] = g[i][j];
    __syncthreads();

    float yd[4][4] = {};
#pragma unroll 4
    for (int s = 0; s < 64; s++) {
        float a[4], bb[4];
#pragma unroll
        for (int i = 0; i < 4; i++) a[i]  = sC[(r0 + i) * 65 + s];
#pragma unroll
        for (int j = 0; j < 4; j++) bb[j] = sX[s * 65 + c0 + j];
#pragma unroll
        for (int i = 0; i < 4; i++)
#pragma unroll
            for (int j = 0; j < 4; j++) yd[i][j] += a[i] * bb[j];
    }
    float st[4][4] = {};
#pragma unroll 4
    for (int l = 0; l < 64; l++) {
        float d = sdec[l];
        float a[4], bb[4];
#pragma unroll
        for (int i = 0; i < 4; i++) a[i]  = sX[l * 65 + r0 + i] * d;
#pragma unroll
        for (int j = 0; j < 4; j++) bb[j] = sB[l * 65 + c0 + j];
#pragma unroll
        for (int i = 0; i < 4; i++)
#pragma unroll
            for (int j = 0; j < 4; j++) st[i][j] += a[i] * bb[j];
    }
    size_t obase = (size_t)tile * 4096;
#pragma unroll
    for (int i = 0; i < 4; i++)
#pragma unroll
        for (int j = 0; j < 4; j++) {
            gYdiag[obase + (r0 + i) * 64 + c0 + j]  = yd[i][j];
            gStates[obase + (r0 + i) * 64 + c0 + j] = st[i][j];
        }
    if (t == 0) gAlast[tile] = sacum[63];
}

// ---------------------------------------------------------------------------
// Chunk-level scan, one element per thread (512 CTAs x 256 thr = 131072 lanes)
// ---------------------------------------------------------------------------
__global__ __launch_bounds__(256)
void scan_kernel(float* __restrict__ out_final) {
    const int bh = blockIdx.x >> 4;            // 0..31
    const int b = bh >> 4, h = bh & 15;
    const int e = ((blockIdx.x & 15) << 8) | threadIdx.x;   // 0..4095
    float S = 0.f;
#pragma unroll 4
    for (int c = 0; c < 64; c++) {
        int tile = (b * 64 + c) * 16 + h;
        float d = expf(gAlast[tile]);
        size_t base = (size_t)tile * 4096 + e;
        gStateIn[base] = S;
        S = S * d + gStates[base];
    }
    out_final[(size_t)Y_ELEMS + (size_t)(b * 16 + h) * 4096 + e] = S;
}

// ---------------------------------------------------------------------------
// SSD pass 2: Y_off + silu gating; writes bf16 hi/lo for the final GEMM
// ---------------------------------------------------------------------------
__global__ __launch_bounds__(256)
void ssd_pass2(const float* __restrict__ Alog) {
    __shared__ float sC[64 * 65];
    __shared__ float sS[64 * 65];
    __shared__ float sdt[64];
    __shared__ float sacum[64];

    const int tile = blockIdx.x;
    const int h = tile & 15;
    const int c = (tile >> 4) & 63;
    const int b = tile >> 10;
    const int t = threadIdx.x;
    const int tokb = b * 4096 + c * 64;

    if (t < 64) sdt[t] = gDt[(size_t)(tokb + t) * NHEADS + h];
    __syncthreads();
    if (t == 0) {
        float expA = expf(Alog[h]);
        float run = 0.f;
        for (int l = 0; l < 64; l++) { run -= expA * sdt[l]; sacum[l] = run; }
    }
    size_t sbase = (size_t)tile * 4096;
#pragma unroll
    for (int k = 0; k < 16; k++) {
        int idx = t + k * 256;
        int l = idx >> 6, n = idx & 63;
        sC[l * 65 + n] = gC[(size_t)(tokb + l) * DMOD + h * 64 + n];
        sS[l * 65 + n] = gStateIn[sbase + idx];
    }
    __syncthreads();

    const int ty = t >> 4, tx = t & 15;
    const int r0 = ty * 4, c0 = tx * 4;
    float o[4][4] = {};
#pragma unroll 4
    for (int n = 0; n < 64; n++) {
        float a[4], bb[4];
#pragma unroll
        for (int i = 0; i < 4; i++) a[i]  = sC[(r0 + i) * 65 + n];
#pragma unroll
        for (int j = 0; j < 4; j++) bb[j] = sS[(c0 + j) * 65 + n];
#pragma unroll
        for (int i = 0; i < 4; i++)
#pragma unroll
            for (int j = 0; j < 4; j++) o[i][j] += a[i] * bb[j];
    }
#pragma unroll
    for (int i = 0; i < 4; i++) {
        int l = r0 + i;
        size_t tok = (size_t)(tokb + l);
        float eA = expf(sacum[l]);
#pragma unroll
        for (int j = 0; j < 4; j++) {
            int p = c0 + j;
            int dcol = h * 64 + p;
            float yv = gYdiag[sbase + l * 64 + p] + o[i][j] * eA;
            float zv = gXZ[tok * 2048 + 1024 + dcol];
            float sig = 1.f / (1.f + expf(-zv));
            float y = yv * (zv * sig);
            __nv_bfloat16 hh = __float2bfloat16(y);
            gYaHi[tok * DMOD + dcol] = hh;
            gYaLo[tok * DMOD + dcol] = __float2bfloat16(y - __bfloat162float(hh));
        }
    }
}

// ---------------------------------------------------------------------------
extern "C" void kernel_launch(void* const* d_in, const int* in_sizes, int n_in,
                              void* d_out, int out_size) {
    const float* x     = (const float*)d_in[0];
    const float* W_in  = (const float*)d_in[1];
    const float* W_dt  = (const float*)d_in[2];
    const float* b_dt  = (const float*)d_in[3];
    const float* W_B   = (const float*)d_in[4];
    const float* W_C   = (const float*)d_in[5];
    const float* W_out = (const float*)d_in[6];
    const float* A_log = (const float*)d_in[7];
    float* out = (float*)d_out;

    void *pXZ, *pB, *pC;
    cudaGetSymbolAddress(&pXZ, gXZ);
    cudaGetSymbolAddress(&pB,  gB);
    cudaGetSymbolAddress(&pC,  gC);
    void *pXhi, *pXlo, *pWinH, *pWinL, *pWBH, *pWBL, *pWCH, *pWCL, *pWoH, *pWoL, *pYaH, *pYaL;
    cudaGetSymbolAddress(&pXhi, gXhi);   cudaGetSymbolAddress(&pXlo, gXlo);
    cudaGetSymbolAddress(&pWinH, gWinHi); cudaGetSymbolAddress(&pWinL, gWinLo);
    cudaGetSymbolAddress(&pWBH, gWBHi);  cudaGetSymbolAddress(&pWBL, gWBLo);
    cudaGetSymbolAddress(&pWCH, gWCHi);  cudaGetSymbolAddress(&pWCL, gWCLo);
    cudaGetSymbolAddress(&pWoH, gWoHi);  cudaGetSymbolAddress(&pWoL, gWoLo);
    cudaGetSymbolAddress(&pYaH, gYaHi);  cudaGetSymbolAddress(&pYaL, gYaLo);

    cudaFuncSetAttribute(gemm_mma, cudaFuncAttributeMaxDynamicSharedMemorySize, GEMM_SMEM);
    const int P1_SHMEM = 3 * 64 * 65 * (int)sizeof(float);
    cudaFuncSetAttribute(ssd_pass1, cudaFuncAttributeMaxDynamicSharedMemorySize, P1_SHMEM);

    // hi/lo conversions
    cvt_hilo<<<(NTOK * DMOD / 4 + 255) / 256, 256>>>(x, (__nv_bfloat16*)pXhi, (__nv_bfloat16*)pXlo, NTOK * DMOD / 4);
    cvt_hilo<<<(2048 * DMOD / 4 + 255) / 256, 256>>>(W_in, (__nv_bfloat16*)pWinH, (__nv_bfloat16*)pWinL, 2048 * DMOD / 4);
    cvt_hilo<<<(DMOD * DMOD / 4 + 255) / 256, 256>>>(W_B, (__nv_bfloat16*)pWBH, (__nv_bfloat16*)pWBL, DMOD * DMOD / 4);
    cvt_hilo<<<(DMOD * DMOD / 4 + 255) / 256, 256>>>(W_C, (__nv_bfloat16*)pWCH, (__nv_bfloat16*)pWCL, DMOD * DMOD / 4);
    cvt_hilo<<<(DMOD * DMOD / 4 + 255) / 256, 256>>>(W_out, (__nv_bfloat16*)pWoH, (__nv_bfloat16*)pWoL, DMOD * DMOD / 4);

    // xz = x @ W_in^T  (8192 x 2048 x 1024)
    gemm_mma<<<dim3(2048 / 128, NTOK / 128), 256, GEMM_SMEM>>>(
        (const __nv_bfloat16*)pXhi, (const __nv_bfloat16*)pXlo,
        (const __nv_bfloat16*)pWinH, (const __nv_bfloat16*)pWinL,
        (float*)pXZ, NTOK, 2048, DMOD);
    dt_kernel<<<NTOK, 512>>>(x, W_dt, b_dt);
    // B, C projections (8192 x 1024 x 1024)
    gemm_mma<<<dim3(1024 / 128, NTOK / 128), 256, GEMM_SMEM>>>(
        (const __nv_bfloat16*)pXhi, (const __nv_bfloat16*)pXlo,
        (const __nv_bfloat16*)pWBH, (const __nv_bfloat16*)pWBL,
        (float*)pB, NTOK, DMOD, DMOD);
    gemm_mma<<<dim3(1024 / 128, NTOK / 128), 256, GEMM_SMEM>>>(
        (const __nv_bfloat16*)pXhi, (const __nv_bfloat16*)pXlo,
        (const __nv_bfloat16*)pWCH, (const __nv_bfloat16*)pWCL,
        (float*)pC, NTOK, DMOD, DMOD);

    ssd_pass1<<<NTILE, 256, P1_SHMEM>>>(A_log);
    scan_kernel<<<512, 256>>>(out);
    ssd_pass2<<<NTILE, 256>>>(A_log);

    // y = Yact @ W_out^T -> d_out
    gemm_mma<<<dim3(1024 / 128, NTOK / 128), 256, GEMM_SMEM>>>(
        (const __nv_bfloat16*)pYaH, (const __nv_bfloat16*)pYaL,
        (const __nv_bfloat16*)pWoH, (const __nv_bfloat16*)pWoL,
        out, NTOK, DMOD, DMOD);
}